// round 12
// baseline (speedup 1.0000x reference)
#include <cuda_runtime.h>
#include <cuda_bf16.h>
#include <cstdint>

#define PB   256
#define PN   512
#define PD   256
#define PDEG 32
#define PEG  (PN * PDEG)          // 16,384 edges per graph
#define PE   (PB * PEG)           // 4,194,304 edges
#define PNN  (PB * PN)            // 131,072 nodes
#define PK   409
#define PBK  (PB * PK)            // 104,704

// Output layout (float32, reference return order)
#define OFF_X     ((size_t)0)
#define OFF_EI    ((size_t)PBK * PD)
#define OFF_MASK  (OFF_EI + (size_t)2 * PE)
#define OFF_BATCH (OFF_MASK + (size_t)PE)
#define OFF_PERM  (OFF_BATCH + (size_t)PBK)

#define EDGE_SMEM_BYTES (PEG * 4)   // 65536: packed (row<<16|col) per edge

__device__ __forceinline__ unsigned int fkey(float f) {
    unsigned int u = __float_as_uint(f);
    return (u & 0x80000000u) ? ~u : (u | 0x80000000u);   // monotonic float->uint
}

__device__ __forceinline__ unsigned long long u64min(unsigned long long a, unsigned long long b) { return a < b ? a : b; }
__device__ __forceinline__ unsigned long long u64max(unsigned long long a, unsigned long long b) { return a > b ? a : b; }

// One CTA per graph. Warp-specialized front (x.W || edge ingest) and tail
// (x_out gather || edge relabel) to keep DRAM busy through smem-only phases.
__global__ void __launch_bounds__(512, 2)
k_fused(const float* __restrict__ x, const int* __restrict__ ei,
        const float* __restrict__ W, const float* __restrict__ bias,
        float* __restrict__ out) {
    extern __shared__ int sedge[];                // 16384 packed edges (64 KB)
    __shared__ float4 sW4[PD / 4];                // 1 KB
    __shared__ float  sh[PN];                     // h, then u (in place)
    __shared__ float  sacc[PN];
    __shared__ int    sdeg[PN];
    __shared__ float  sscore[PN];
    __shared__ unsigned long long sk[PN];         // 4 KB sort keys
    __shared__ int    sflag[PN];
    __shared__ int    swsum[PN / 32];
    __shared__ int    skeep[PN];                  // global new idx or -1
    __shared__ int    sperm[PK];                  // rank -> local node idx

    const int g    = blockIdx.x;
    const int t    = threadIdx.x;                 // 0..511
    const int warp = t >> 5, lane = t & 31;

    const int4* row4 = reinterpret_cast<const int4*>(ei + (size_t)g * PEG);
    const int4* col4 = reinterpret_cast<const int4*>(ei + (size_t)PE + (size_t)g * PEG);
    int4* sedge4 = reinterpret_cast<int4*>(sedge);

    // ---- Phase 0: init + W load ----
    if (t < PD / 4) sW4[t] = reinterpret_cast<const float4*>(W)[t];
    sdeg[t] = 1;                                  // self loop
    sacc[t] = 0.0f;
    sflag[t] = 0;
    __syncthreads();

    // ---- Phase 1 || 2: warps 0-11 compute h = x.W; warps 12-15 ingest edges ----
    if (warp < 12) {
        const float4* xg = reinterpret_cast<const float4*>(x + (size_t)g * PN * PD);
        for (int row = warp; row < PN; row += 12) {
            const float4* xr = xg + (size_t)row * (PD / 4);
            float4 a = xr[lane];
            float4 b = xr[lane + 32];
            float4 wa = sW4[lane];
            float4 wb = sW4[lane + 32];
            float s = a.x * wa.x + a.y * wa.y + a.z * wa.z + a.w * wa.w
                    + b.x * wb.x + b.y * wb.y + b.z * wb.z + b.w * wb.w;
            #pragma unroll
            for (int o = 16; o > 0; o >>= 1) s += __shfl_down_sync(0xffffffffu, s, o);
            if (lane == 0) sh[row] = s;
        }
    } else {
        const int w2 = warp - 12;                 // 0..3
        #pragma unroll 4
        for (int i = 0; i < 32; i++) {            // 4 warps x 32 iters x 32 lanes = 4096 int4
            int idx = w2 * 1024 + i * 32 + lane;
            int4 r = __ldcs(&row4[idx]);
            int4 c = __ldcs(&col4[idx]);
            int4 p;
            p.x = ((r.x & (PN - 1)) << 16) | (c.x & (PN - 1));
            p.y = ((r.y & (PN - 1)) << 16) | (c.y & (PN - 1));
            p.z = ((r.z & (PN - 1)) << 16) | (c.z & (PN - 1));
            p.w = ((r.w & (PN - 1)) << 16) | (c.w & (PN - 1));
            sedge4[idx] = p;
            atomicAdd(&sdeg[p.x & 0xFFFF], 1);
            atomicAdd(&sdeg[p.y & 0xFFFF], 1);
            atomicAdd(&sdeg[p.z & 0xFFFF], 1);
            atomicAdd(&sdeg[p.w & 0xFFFF], 1);
        }
    }
    __syncthreads();

    // ---- Phase 3: u[v] = rsqrt(deg)*h  (in place) ----
    sh[t] = rsqrtf((float)sdeg[t]) * sh[t];
    __syncthreads();

    // ---- Phase 4: acc[col] += u[row]  (edges from smem) ----
    #pragma unroll
    for (int i = 0; i < PEG / 4 / PN; i++) {
        int4 p = sedge4[t + i * PN];
        float u0 = sh[p.x >> 16];
        float u1 = sh[p.y >> 16];
        float u2 = sh[p.z >> 16];
        float u3 = sh[p.w >> 16];
        atomicAdd(&sacc[p.x & 0xFFFF], u0);
        atomicAdd(&sacc[p.y & 0xFFFF], u1);
        atomicAdd(&sacc[p.z & 0xFFFF], u2);
        atomicAdd(&sacc[p.w & 0xFFFF], u3);
    }
    __syncthreads();

    // ---- Phase 5: score + bitonic top-K (warp-shuffle hybrid) ----
    float s = rsqrtf((float)sdeg[t]) * (sacc[t] + sh[t]) + __ldg(bias);
    sscore[t] = s;
    unsigned long long v =
        (((unsigned long long)fkey(s)) << 9) | (unsigned long long)(511 - t);

    #pragma unroll
    for (unsigned int k = 2; k <= 32; k <<= 1) {
        #pragma unroll
        for (unsigned int j = k >> 1; j > 0; j >>= 1) {
            unsigned long long o = __shfl_xor_sync(0xffffffffu, v, j);
            bool up = ((t & k) == 0);
            bool keep_min = (up == ((t & j) == 0));
            v = keep_min ? u64min(v, o) : u64max(v, o);
        }
    }
    sk[t] = v;
    __syncthreads();

    #pragma unroll
    for (unsigned int k = 64; k <= (unsigned int)PN; k <<= 1) {
        for (unsigned int j = k >> 1; j >= 32; j >>= 1) {
            unsigned int i = (unsigned int)t;
            unsigned int ixj = i ^ j;
            if (ixj > i) {
                bool up = ((i & k) == 0);
                unsigned long long a = sk[i], b = sk[ixj];
                if (up ? (a > b) : (a < b)) { sk[i] = b; sk[ixj] = a; }
            }
            __syncthreads();
        }
        v = sk[t];
        #pragma unroll
        for (unsigned int j = 16; j > 0; j >>= 1) {
            unsigned long long o = __shfl_xor_sync(0xffffffffu, v, j);
            bool up = ((t & k) == 0);
            bool keep_min = (up == ((t & j) == 0));
            v = keep_min ? u64min(v, o) : u64max(v, o);
        }
        sk[t] = v;
        __syncthreads();
    }

    if (t >= PN - PK) {
        int li = 511 - (int)(sk[t] & 511ull);
        sflag[li] = 1;
    }
    __syncthreads();

    // ---- Phase 6: ranks via ballot scan ----
    bool kept = (sflag[t] != 0);
    unsigned int bal = __ballot_sync(0xffffffffu, kept);
    int wpre = __popc(bal & ((1u << lane) - 1u));
    if (lane == 31) swsum[warp] = wpre + (kept ? 1 : 0);
    __syncthreads();

    if (kept) {
        int base = 0;
        #pragma unroll
        for (int w = 0; w < PN / 32; w++) base += (w < warp) ? swsum[w] : 0;
        int rank = base + wpre;
        int gi = g * PK + rank;
        skeep[t] = gi;
        sperm[rank] = t;
        __stcs(&out[OFF_PERM + gi],  (float)(g * PN + t));
        __stcs(&out[OFF_BATCH + gi], (float)g);
    } else {
        skeep[t] = -1;
    }
    __syncthreads();

    // ---- Phase 7 || 8: warps 0-12 gather x_out; warps 13-15 relabel edges ----
    if (warp < 13) {
        const float4* xg = reinterpret_cast<const float4*>(x + (size_t)g * PN * PD);
        for (int row = warp; row < PK; row += 13) {
            int p = sperm[row];
            float tsc = tanhf(sscore[p]);
            const float4* xr = xg + (size_t)p * (PD / 4);
            float4* orow = reinterpret_cast<float4*>(
                out + OFF_X + (size_t)(g * PK + row) * PD);
            float4 a = xr[lane];
            float4 b = xr[lane + 32];
            a.x *= tsc; a.y *= tsc; a.z *= tsc; a.w *= tsc;
            b.x *= tsc; b.y *= tsc; b.z *= tsc; b.w *= tsc;
            __stcs(&orow[lane], a);
            __stcs(&orow[lane + 32], b);
        }
    } else {
        float4* oei_r = reinterpret_cast<float4*>(out + OFF_EI) + (size_t)g * (PEG / 4);
        float4* oei_c = reinterpret_cast<float4*>(out + OFF_EI + (size_t)PE) + (size_t)g * (PEG / 4);
        float4* omsk  = reinterpret_cast<float4*>(out + OFF_MASK) + (size_t)g * (PEG / 4);
        const int w2 = warp - 13;                 // 0..2
        for (int idx = w2 * 32 + lane; idx < PEG / 4; idx += 96) {
            int4 p = sedge4[idx];
            int a0 = skeep[p.x >> 16],    b0 = skeep[p.x & 0xFFFF];
            int a1 = skeep[p.y >> 16],    b1 = skeep[p.y & 0xFFFF];
            int a2 = skeep[p.z >> 16],    b2 = skeep[p.z & 0xFFFF];
            int a3 = skeep[p.w >> 16],    b3 = skeep[p.w & 0xFFFF];
            bool m0 = (a0 >= 0) && (b0 >= 0);
            bool m1 = (a1 >= 0) && (b1 >= 0);
            bool m2 = (a2 >= 0) && (b2 >= 0);
            bool m3 = (a3 >= 0) && (b3 >= 0);
            float4 fr, fc, fm;
            fr.x = m0 ? (float)a0 : -1.0f; fc.x = m0 ? (float)b0 : -1.0f; fm.x = m0 ? 1.0f : 0.0f;
            fr.y = m1 ? (float)a1 : -1.0f; fc.y = m1 ? (float)b1 : -1.0f; fm.y = m1 ? 1.0f : 0.0f;
            fr.z = m2 ? (float)a2 : -1.0f; fc.z = m2 ? (float)b2 : -1.0f; fm.z = m2 ? 1.0f : 0.0f;
            fr.w = m3 ? (float)a3 : -1.0f; fc.w = m3 ? (float)b3 : -1.0f; fm.w = m3 ? 1.0f : 0.0f;
            __stcs(&oei_r[idx], fr);
            __stcs(&oei_c[idx], fc);
            __stcs(&omsk[idx],  fm);
        }
    }
}

extern "C" void kernel_launch(void* const* d_in, const int* in_sizes, int n_in,
                              void* d_out, int out_size) {
    const float* x  = (const float*)d_in[0];
    const int*   ei = (const int*)d_in[1];
    const float* W  = (const float*)d_in[3];
    const float* b  = (const float*)d_in[4];
    float* out = (float*)d_out;

    static bool configured = false;
    if (!configured) {
        cudaFuncSetAttribute(k_fused, cudaFuncAttributeMaxDynamicSharedMemorySize,
                             EDGE_SMEM_BYTES);
        configured = true;
    }
    k_fused<<<PB, PN, EDGE_SMEM_BYTES>>>(x, ei, W, b, out);
}

// round 14
// speedup vs baseline: 1.0398x; 1.0398x over previous
#include <cuda_runtime.h>
#include <cuda_bf16.h>
#include <cstdint>

#define PB   256
#define PN   512
#define PD   256
#define PDEG 32
#define PEG  (PN * PDEG)          // 16,384 edges per graph
#define PE   (PB * PEG)           // 4,194,304 edges
#define PNN  (PB * PN)            // 131,072 nodes
#define PK   409
#define PBK  (PB * PK)            // 104,704

// Output layout (float32, reference return order)
#define OFF_X     ((size_t)0)
#define OFF_EI    ((size_t)PBK * PD)
#define OFF_MASK  (OFF_EI + (size_t)2 * PE)
#define OFF_BATCH (OFF_MASK + (size_t)PE)
#define OFF_PERM  (OFF_BATCH + (size_t)PBK)

#define EDGE_SMEM_BYTES (PEG * 4)   // 65536: packed (row<<16|col) per edge

__device__ __forceinline__ unsigned int fkey(float f) {
    unsigned int u = __float_as_uint(f);
    return (u & 0x80000000u) ? ~u : (u | 0x80000000u);   // monotonic float->uint
}

__device__ __forceinline__ unsigned long long u64min(unsigned long long a, unsigned long long b) { return a < b ? a : b; }
__device__ __forceinline__ unsigned long long u64max(unsigned long long a, unsigned long long b) { return a > b ? a : b; }

// One CTA per graph. Edge ingest is interleaved into the x.W stream and edge
// relabel into the x_out gather stream — every warp issues both streams.
__global__ void __launch_bounds__(512, 2)
k_fused(const float* __restrict__ x, const int* __restrict__ ei,
        const float* __restrict__ W, const float* __restrict__ bias,
        float* __restrict__ out) {
    extern __shared__ int sedge[];                // 16384 packed edges (64 KB)
    __shared__ float4 sW4[PD / 4];                // 1 KB
    __shared__ float  sh[PN];                     // h, then u (in place)
    __shared__ float  sacc[PN];
    __shared__ int    sdeg[PN];
    __shared__ float  sscore[PN];
    __shared__ unsigned long long sk[PN];         // 4 KB sort keys
    __shared__ int    sflag[PN];
    __shared__ int    swsum[PN / 32];
    __shared__ int    skeep[PN];                  // global new idx or -1
    __shared__ int    sperm[PK];                  // rank -> local node idx

    const int g    = blockIdx.x;
    const int t    = threadIdx.x;                 // 0..511
    const int warp = t >> 5, lane = t & 31;

    const int4* row4 = reinterpret_cast<const int4*>(ei + (size_t)g * PEG);
    const int4* col4 = reinterpret_cast<const int4*>(ei + (size_t)PE + (size_t)g * PEG);
    int4* sedge4 = reinterpret_cast<int4*>(sedge);

    // ---- Phase 0: init + W load ----
    if (t < PD / 4) sW4[t] = reinterpret_cast<const float4*>(W)[t];
    sdeg[t] = 1;                                  // self loop
    sacc[t] = 0.0f;
    sflag[t] = 0;
    __syncthreads();

    // ---- Phase 1+2 fused: h = x.W (warp per row) with edge ingest slotted in ----
    {
        const float4* xg = reinterpret_cast<const float4*>(x + (size_t)g * PN * PD);
        #pragma unroll 4
        for (int i = 0; i < 32; i++) {
            // edge ingest: one int4 per lane on every 4th iteration
            if ((i & 3) == 0) {
                int eidx = (warp * 8 + (i >> 2)) * 32 + lane;   // 0..4095, coalesced
                int4 r = __ldcs(&row4[eidx]);
                int4 c = __ldcs(&col4[eidx]);
                int4 p;
                p.x = ((r.x & (PN - 1)) << 16) | (c.x & (PN - 1));
                p.y = ((r.y & (PN - 1)) << 16) | (c.y & (PN - 1));
                p.z = ((r.z & (PN - 1)) << 16) | (c.z & (PN - 1));
                p.w = ((r.w & (PN - 1)) << 16) | (c.w & (PN - 1));
                sedge4[eidx] = p;
                atomicAdd(&sdeg[p.x & 0xFFFF], 1);
                atomicAdd(&sdeg[p.y & 0xFFFF], 1);
                atomicAdd(&sdeg[p.z & 0xFFFF], 1);
                atomicAdd(&sdeg[p.w & 0xFFFF], 1);
            }
            int row = warp * 32 + i;
            const float4* xr = xg + (size_t)row * (PD / 4);
            float4 a = xr[lane];
            float4 b = xr[lane + 32];
            float4 wa = sW4[lane];
            float4 wb = sW4[lane + 32];
            float s = a.x * wa.x + a.y * wa.y + a.z * wa.z + a.w * wa.w
                    + b.x * wb.x + b.y * wb.y + b.z * wb.z + b.w * wb.w;
            #pragma unroll
            for (int o = 16; o > 0; o >>= 1) s += __shfl_down_sync(0xffffffffu, s, o);
            if (lane == 0) sh[row] = s;
        }
    }
    __syncthreads();

    // ---- Phase 3: u[v] = rsqrt(deg)*h  (in place) ----
    sh[t] = rsqrtf((float)sdeg[t]) * sh[t];
    __syncthreads();

    // ---- Phase 4: acc[col] += u[row]  (edges from smem) ----
    #pragma unroll
    for (int i = 0; i < PEG / 4 / PN; i++) {
        int4 p = sedge4[t + i * PN];
        float u0 = sh[p.x >> 16];
        float u1 = sh[p.y >> 16];
        float u2 = sh[p.z >> 16];
        float u3 = sh[p.w >> 16];
        atomicAdd(&sacc[p.x & 0xFFFF], u0);
        atomicAdd(&sacc[p.y & 0xFFFF], u1);
        atomicAdd(&sacc[p.z & 0xFFFF], u2);
        atomicAdd(&sacc[p.w & 0xFFFF], u3);
    }
    __syncthreads();

    // ---- Phase 5: score + bitonic top-K (warp-shuffle hybrid) ----
    float s = rsqrtf((float)sdeg[t]) * (sacc[t] + sh[t]) + __ldg(bias);
    sscore[t] = s;
    unsigned long long v =
        (((unsigned long long)fkey(s)) << 9) | (unsigned long long)(511 - t);

    #pragma unroll
    for (unsigned int k = 2; k <= 32; k <<= 1) {
        #pragma unroll
        for (unsigned int j = k >> 1; j > 0; j >>= 1) {
            unsigned long long o = __shfl_xor_sync(0xffffffffu, v, j);
            bool up = ((t & k) == 0);
            bool keep_min = (up == ((t & j) == 0));
            v = keep_min ? u64min(v, o) : u64max(v, o);
        }
    }
    sk[t] = v;
    __syncthreads();

    #pragma unroll
    for (unsigned int k = 64; k <= (unsigned int)PN; k <<= 1) {
        for (unsigned int j = k >> 1; j >= 32; j >>= 1) {
            unsigned int i = (unsigned int)t;
            unsigned int ixj = i ^ j;
            if (ixj > i) {
                bool up = ((i & k) == 0);
                unsigned long long a = sk[i], b = sk[ixj];
                if (up ? (a > b) : (a < b)) { sk[i] = b; sk[ixj] = a; }
            }
            __syncthreads();
        }
        v = sk[t];
        #pragma unroll
        for (unsigned int j = 16; j > 0; j >>= 1) {
            unsigned long long o = __shfl_xor_sync(0xffffffffu, v, j);
            bool up = ((t & k) == 0);
            bool keep_min = (up == ((t & j) == 0));
            v = keep_min ? u64min(v, o) : u64max(v, o);
        }
        sk[t] = v;
        __syncthreads();
    }

    if (t >= PN - PK) {
        int li = 511 - (int)(sk[t] & 511ull);
        sflag[li] = 1;
    }
    __syncthreads();

    // ---- Phase 6: ranks via ballot scan ----
    bool kept = (sflag[t] != 0);
    unsigned int bal = __ballot_sync(0xffffffffu, kept);
    int wpre = __popc(bal & ((1u << lane) - 1u));
    if (lane == 31) swsum[warp] = wpre + (kept ? 1 : 0);
    __syncthreads();

    if (kept) {
        int base = 0;
        #pragma unroll
        for (int w = 0; w < PN / 32; w++) base += (w < warp) ? swsum[w] : 0;
        int rank = base + wpre;
        int gi = g * PK + rank;
        skeep[t] = gi;
        sperm[rank] = t;
        __stcs(&out[OFF_PERM + gi],  (float)(g * PN + t));
        __stcs(&out[OFF_BATCH + gi], (float)g);
    } else {
        skeep[t] = -1;
    }
    __syncthreads();

    // ---- Phase 7+8 fused: x_out gather (warp per row) with edge relabel slotted in ----
    {
        const float4* xg = reinterpret_cast<const float4*>(x + (size_t)g * PN * PD);
        float4* oei_r = reinterpret_cast<float4*>(out + OFF_EI) + (size_t)g * (PEG / 4);
        float4* oei_c = reinterpret_cast<float4*>(out + OFF_EI + (size_t)PE) + (size_t)g * (PEG / 4);
        float4* omsk  = reinterpret_cast<float4*>(out + OFF_MASK) + (size_t)g * (PEG / 4);

        int row = warp;
        for (int it = 0; it < 26; it++, row += 16) {
            // edge relabel: one int4 per lane on the first 8 iterations
            if (it < 8) {
                int eidx = (warp * 8 + it) * 32 + lane;    // 0..4095, coalesced
                int4 p = sedge4[eidx];
                int a0 = skeep[p.x >> 16], b0 = skeep[p.x & 0xFFFF];
                int a1 = skeep[p.y >> 16], b1 = skeep[p.y & 0xFFFF];
                int a2 = skeep[p.z >> 16], b2 = skeep[p.z & 0xFFFF];
                int a3 = skeep[p.w >> 16], b3 = skeep[p.w & 0xFFFF];
                bool m0 = (a0 >= 0) && (b0 >= 0);
                bool m1 = (a1 >= 0) && (b1 >= 0);
                bool m2 = (a2 >= 0) && (b2 >= 0);
                bool m3 = (a3 >= 0) && (b3 >= 0);
                float4 fr, fc, fm;
                fr.x = m0 ? (float)a0 : -1.0f; fc.x = m0 ? (float)b0 : -1.0f; fm.x = m0 ? 1.0f : 0.0f;
                fr.y = m1 ? (float)a1 : -1.0f; fc.y = m1 ? (float)b1 : -1.0f; fm.y = m1 ? 1.0f : 0.0f;
                fr.z = m2 ? (float)a2 : -1.0f; fc.z = m2 ? (float)b2 : -1.0f; fm.z = m2 ? 1.0f : 0.0f;
                fr.w = m3 ? (float)a3 : -1.0f; fc.w = m3 ? (float)b3 : -1.0f; fm.w = m3 ? 1.0f : 0.0f;
                __stcs(&oei_r[eidx], fr);
                __stcs(&oei_c[eidx], fc);
                __stcs(&omsk[eidx],  fm);
            }
            if (row < PK) {
                int p = sperm[row];
                float tsc = tanhf(sscore[p]);
                const float4* xr = xg + (size_t)p * (PD / 4);
                float4* orow = reinterpret_cast<float4*>(
                    out + OFF_X + (size_t)(g * PK + row) * PD);
                float4 a = xr[lane];
                float4 b = xr[lane + 32];
                a.x *= tsc; a.y *= tsc; a.z *= tsc; a.w *= tsc;
                b.x *= tsc; b.y *= tsc; b.z *= tsc; b.w *= tsc;
                __stcs(&orow[lane], a);
                __stcs(&orow[lane + 32], b);
            }
        }
    }
}

extern "C" void kernel_launch(void* const* d_in, const int* in_sizes, int n_in,
                              void* d_out, int out_size) {
    const float* x  = (const float*)d_in[0];
    const int*   ei = (const int*)d_in[1];
    const float* W  = (const float*)d_in[3];
    const float* b  = (const float*)d_in[4];
    float* out = (float*)d_out;

    static bool configured = false;
    if (!configured) {
        cudaFuncSetAttribute(k_fused, cudaFuncAttributeMaxDynamicSharedMemorySize,
                             EDGE_SMEM_BYTES);
        configured = true;
    }
    k_fused<<<PB, PN, EDGE_SMEM_BYTES>>>(x, ei, W, b, out);
}

// round 15
// speedup vs baseline: 1.1003x; 1.0582x over previous
#include <cuda_runtime.h>
#include <cuda_bf16.h>
#include <cstdint>

#define PB   256
#define PN   512
#define PD   256
#define PDEG 32
#define PEG  (PN * PDEG)          // 16,384 edges per graph
#define PE   (PB * PEG)           // 4,194,304 edges
#define PNN  (PB * PN)            // 131,072 nodes
#define PK   409
#define PBK  (PB * PK)            // 104,704

// Output layout (float32, reference return order)
#define OFF_X     ((size_t)0)
#define OFF_EI    ((size_t)PBK * PD)
#define OFF_MASK  (OFF_EI + (size_t)2 * PE)
#define OFF_BATCH (OFF_MASK + (size_t)PE)
#define OFF_PERM  (OFF_BATCH + (size_t)PBK)

#define EDGE_SMEM_BYTES (PEG * 4)   // 64 KB: col ids, later packed (row<<16|col)

__device__ __forceinline__ unsigned int fkey(float f) {
    unsigned int u = __float_as_uint(f);
    return (u & 0x80000000u) ? ~u : (u | 0x80000000u);   // monotonic float->uint
}

__device__ __forceinline__ unsigned long long u64min(unsigned long long a, unsigned long long b) { return a < b ? a : b; }
__device__ __forceinline__ unsigned long long u64max(unsigned long long a, unsigned long long b) { return a > b ? a : b; }

__device__ __forceinline__ unsigned int smem_u32(const void* p) {
    return (unsigned int)__cvta_generic_to_shared(p);
}

// One CTA per graph. Edge col list is prefetched via cp.async (register-free)
// under the phase-1 x stream; row list streams in under the phase-4 atomics.
__global__ void __launch_bounds__(512, 2)
k_fused(const float* __restrict__ x, const int* __restrict__ ei,
        const float* __restrict__ W, const float* __restrict__ bias,
        float* __restrict__ out) {
    extern __shared__ int sedge[];                // 16384 ints (64 KB)
    __shared__ float4 sW4[PD / 4];                // 1 KB
    __shared__ float  sh[PN];                     // h, then u (in place)
    __shared__ float  sacc[PN];
    __shared__ int    sdeg[PN];
    __shared__ float  sscore[PN];
    __shared__ unsigned long long sk[PN];         // 4 KB sort keys
    __shared__ int    sflag[PN];
    __shared__ int    swsum[PN / 32];
    __shared__ int    skeep[PN];                  // global new idx or -1
    __shared__ int    sperm[PK];                  // rank -> local node idx

    const int g    = blockIdx.x;
    const int t    = threadIdx.x;                 // 0..511
    const int warp = t >> 5, lane = t & 31;

    const int4* row4 = reinterpret_cast<const int4*>(ei + (size_t)g * PEG);
    const int4* col4 = reinterpret_cast<const int4*>(ei + (size_t)PE + (size_t)g * PEG);
    int4* sedge4 = reinterpret_cast<int4*>(sedge);

    // ---- Prologue: async prefetch of the col list (8 x 16B per thread) ----
    {
        unsigned int dst = smem_u32(sedge);
        #pragma unroll
        for (int i = 0; i < PEG / 4 / PN; i++) {      // 8 iterations
            int idx = t + i * PN;
            asm volatile("cp.async.cg.shared.global [%0], [%1], 16;\n"
                         :: "r"(dst + idx * 16), "l"(col4 + idx));
        }
        asm volatile("cp.async.commit_group;\n");
    }

    // ---- Phase 0: init + W load ----
    if (t < PD / 4) sW4[t] = reinterpret_cast<const float4*>(W)[t];
    sdeg[t] = 1;                                  // self loop
    sacc[t] = 0.0f;
    sflag[t] = 0;
    __syncthreads();

    // ---- Phase 1: h = x.W  — warp per row, clean stream ----
    {
        const float4* xg = reinterpret_cast<const float4*>(x + (size_t)g * PN * PD);
        #pragma unroll 4
        for (int i = 0; i < PN / 16; i++) {       // 32 iterations
            int row = warp * 32 + i;
            const float4* xr = xg + (size_t)row * (PD / 4);
            float4 a = xr[lane];
            float4 b = xr[lane + 32];
            float4 wa = sW4[lane];
            float4 wb = sW4[lane + 32];
            float s = a.x * wa.x + a.y * wa.y + a.z * wa.z + a.w * wa.w
                    + b.x * wb.x + b.y * wb.y + b.z * wb.z + b.w * wb.w;
            #pragma unroll
            for (int o = 16; o > 0; o >>= 1) s += __shfl_down_sync(0xffffffffu, s, o);
            if (lane == 0) sh[row] = s;
        }
    }

    // ---- Phase 2: degree count from prefetched smem col ----
    asm volatile("cp.async.wait_group 0;\n");
    __syncthreads();
    #pragma unroll
    for (int i = 0; i < PEG / 4 / PN; i++) {
        int4 c = sedge4[t + i * PN];
        atomicAdd(&sdeg[c.x & (PN - 1)], 1);
        atomicAdd(&sdeg[c.y & (PN - 1)], 1);
        atomicAdd(&sdeg[c.z & (PN - 1)], 1);
        atomicAdd(&sdeg[c.w & (PN - 1)], 1);
    }
    __syncthreads();

    // ---- Phase 3: u[v] = rsqrt(deg)*h  (in place) ----
    sh[t] = rsqrtf((float)sdeg[t]) * sh[t];
    __syncthreads();

    // ---- Phase 4: acc[col] += u[row]; row streamed from global, packed in place ----
    #pragma unroll
    for (int i = 0; i < PEG / 4 / PN; i++) {
        int idx = t + i * PN;
        int4 r = __ldcs(&row4[idx]);
        int4 c = sedge4[idx];
        float u0 = sh[r.x & (PN - 1)];
        float u1 = sh[r.y & (PN - 1)];
        float u2 = sh[r.z & (PN - 1)];
        float u3 = sh[r.w & (PN - 1)];
        int4 p;
        p.x = ((r.x & (PN - 1)) << 16) | (c.x & (PN - 1));
        p.y = ((r.y & (PN - 1)) << 16) | (c.y & (PN - 1));
        p.z = ((r.z & (PN - 1)) << 16) | (c.z & (PN - 1));
        p.w = ((r.w & (PN - 1)) << 16) | (c.w & (PN - 1));
        sedge4[idx] = p;
        atomicAdd(&sacc[p.x & 0xFFFF], u0);
        atomicAdd(&sacc[p.y & 0xFFFF], u1);
        atomicAdd(&sacc[p.z & 0xFFFF], u2);
        atomicAdd(&sacc[p.w & 0xFFFF], u3);
    }
    __syncthreads();

    // ---- Phase 5: score + bitonic top-K (warp-shuffle hybrid) ----
    float s = rsqrtf((float)sdeg[t]) * (sacc[t] + sh[t]) + __ldg(bias);
    sscore[t] = s;
    unsigned long long v =
        (((unsigned long long)fkey(s)) << 9) | (unsigned long long)(511 - t);

    #pragma unroll
    for (unsigned int k = 2; k <= 32; k <<= 1) {
        #pragma unroll
        for (unsigned int j = k >> 1; j > 0; j >>= 1) {
            unsigned long long o = __shfl_xor_sync(0xffffffffu, v, j);
            bool up = ((t & k) == 0);
            bool keep_min = (up == ((t & j) == 0));
            v = keep_min ? u64min(v, o) : u64max(v, o);
        }
    }
    sk[t] = v;
    __syncthreads();

    #pragma unroll
    for (unsigned int k = 64; k <= (unsigned int)PN; k <<= 1) {
        for (unsigned int j = k >> 1; j >= 32; j >>= 1) {
            unsigned int i = (unsigned int)t;
            unsigned int ixj = i ^ j;
            if (ixj > i) {
                bool up = ((i & k) == 0);
                unsigned long long a = sk[i], b = sk[ixj];
                if (up ? (a > b) : (a < b)) { sk[i] = b; sk[ixj] = a; }
            }
            __syncthreads();
        }
        v = sk[t];
        #pragma unroll
        for (unsigned int j = 16; j > 0; j >>= 1) {
            unsigned long long o = __shfl_xor_sync(0xffffffffu, v, j);
            bool up = ((t & k) == 0);
            bool keep_min = (up == ((t & j) == 0));
            v = keep_min ? u64min(v, o) : u64max(v, o);
        }
        sk[t] = v;
        __syncthreads();
    }

    if (t >= PN - PK) {
        int li = 511 - (int)(sk[t] & 511ull);
        sflag[li] = 1;
    }
    __syncthreads();

    // ---- Phase 6: ranks via ballot scan ----
    bool kept = (sflag[t] != 0);
    unsigned int bal = __ballot_sync(0xffffffffu, kept);
    int wpre = __popc(bal & ((1u << lane) - 1u));
    if (lane == 31) swsum[warp] = wpre + (kept ? 1 : 0);
    __syncthreads();

    if (kept) {
        int base = 0;
        #pragma unroll
        for (int w = 0; w < PN / 32; w++) base += (w < warp) ? swsum[w] : 0;
        int rank = base + wpre;
        int gi = g * PK + rank;
        skeep[t] = gi;
        sperm[rank] = t;
        __stcs(&out[OFF_PERM + gi],  (float)(g * PN + t));
        __stcs(&out[OFF_BATCH + gi], (float)g);
    } else {
        skeep[t] = -1;
    }
    __syncthreads();

    // ---- Phase 7: x_out = x[perm] * tanh(score[perm])  — warp per row ----
    {
        const float4* xg = reinterpret_cast<const float4*>(x + (size_t)g * PN * PD);
        for (int row = warp; row < PK; row += 16) {
            int p = sperm[row];
            float tsc = tanhf(sscore[p]);
            const float4* xr = xg + (size_t)p * (PD / 4);
            float4* orow = reinterpret_cast<float4*>(
                out + OFF_X + (size_t)(g * PK + row) * PD);
            float4 a = xr[lane];
            float4 b = xr[lane + 32];
            a.x *= tsc; a.y *= tsc; a.z *= tsc; a.w *= tsc;
            b.x *= tsc; b.y *= tsc; b.z *= tsc; b.w *= tsc;
            __stcs(&orow[lane], a);
            __stcs(&orow[lane + 32], b);
        }
    }

    // ---- Phase 8: edge relabel + mask (edges from smem) ----
    {
        float4* oei_r = reinterpret_cast<float4*>(out + OFF_EI) + (size_t)g * (PEG / 4);
        float4* oei_c = reinterpret_cast<float4*>(out + OFF_EI + (size_t)PE) + (size_t)g * (PEG / 4);
        float4* omsk  = reinterpret_cast<float4*>(out + OFF_MASK) + (size_t)g * (PEG / 4);
        #pragma unroll
        for (int i = 0; i < PEG / 4 / PN; i++) {
            int idx = t + i * PN;
            int4 p = sedge4[idx];
            int a0 = skeep[p.x >> 16],    b0 = skeep[p.x & 0xFFFF];
            int a1 = skeep[p.y >> 16],    b1 = skeep[p.y & 0xFFFF];
            int a2 = skeep[p.z >> 16],    b2 = skeep[p.z & 0xFFFF];
            int a3 = skeep[p.w >> 16],    b3 = skeep[p.w & 0xFFFF];
            bool m0 = (a0 >= 0) && (b0 >= 0);
            bool m1 = (a1 >= 0) && (b1 >= 0);
            bool m2 = (a2 >= 0) && (b2 >= 0);
            bool m3 = (a3 >= 0) && (b3 >= 0);
            float4 fr, fc, fm;
            fr.x = m0 ? (float)a0 : -1.0f; fc.x = m0 ? (float)b0 : -1.0f; fm.x = m0 ? 1.0f : 0.0f;
            fr.y = m1 ? (float)a1 : -1.0f; fc.y = m1 ? (float)b1 : -1.0f; fm.y = m1 ? 1.0f : 0.0f;
            fr.z = m2 ? (float)a2 : -1.0f; fc.z = m2 ? (float)b2 : -1.0f; fm.z = m2 ? 1.0f : 0.0f;
            fr.w = m3 ? (float)a3 : -1.0f; fc.w = m3 ? (float)b3 : -1.0f; fm.w = m3 ? 1.0f : 0.0f;
            __stcs(&oei_r[idx], fr);
            __stcs(&oei_c[idx], fc);
            __stcs(&omsk[idx],  fm);
        }
    }
}

extern "C" void kernel_launch(void* const* d_in, const int* in_sizes, int n_in,
                              void* d_out, int out_size) {
    const float* x  = (const float*)d_in[0];
    const int*   ei = (const int*)d_in[1];
    const float* W  = (const float*)d_in[3];
    const float* b  = (const float*)d_in[4];
    float* out = (float*)d_out;

    static bool configured = false;
    if (!configured) {
        cudaFuncSetAttribute(k_fused, cudaFuncAttributeMaxDynamicSharedMemorySize,
                             EDGE_SMEM_BYTES);
        configured = true;
    }
    k_fused<<<PB, PN, EDGE_SMEM_BYTES>>>(x, ei, W, b, out);
}